// round 13
// baseline (speedup 1.0000x reference)
#include <cuda_runtime.h>
#include <math.h>

#define S_LEN 16384
#define DIM   1024
#define HID   1024
#define G4    4096   // 4*HID
#define NLSTM 128    // lstm CTAs (1/SM)
#define NGEMM 20     // persistent gemm worker CTAs (separate SMs)

// ---------------- scratch (no allocations allowed) ----------------
__device__ float g_xg[(size_t)S_LEN * G4];                  // 256 MB: input gates
__device__ unsigned long long g_hpub[(size_t)S_LEN * HID];  // 128 MB: (tag<<32)|h
__device__ float g_alpha[S_LEN];
__device__ unsigned g_epoch;                                // bumped once per launch
__device__ unsigned g_xgcnt[128];                           // per-rowblock tile count
__device__ unsigned g_xgflag[128];                          // rowblock completion count

// ---------------- helpers ----------------
__device__ __forceinline__ float fsigmoid(float x) {
    return __fdividef(1.0f, 1.0f + __expf(-x));
}
__device__ __forceinline__ float ftanh(float x) {
    float e = __expf(2.0f * x);
    return 1.0f - __fdividef(2.0f, e + 1.0f);
}
__device__ __forceinline__ unsigned long long fma2(unsigned long long a,
                                                   unsigned long long b,
                                                   unsigned long long c) {
    unsigned long long d;
    asm("fma.rn.f32x2 %0, %1, %2, %3;" : "=l"(d) : "l"(a), "l"(b), "l"(c));
    return d;
}
__device__ __forceinline__ unsigned long long packf2(float x, float y) {
    unsigned long long d;
    asm("mov.b64 %0, {%1, %2};" : "=l"(d) : "f"(x), "f"(y));
    return d;
}
__device__ __forceinline__ float lo_f(unsigned long long v) {
    return __uint_as_float((unsigned)v);
}
__device__ __forceinline__ float hi_f(unsigned long long v) {
    return __uint_as_float((unsigned)(v >> 32));
}
__device__ __forceinline__ unsigned long long ldrelax64(const unsigned long long* p) {
    unsigned long long v;
    asm volatile("ld.relaxed.gpu.global.u64 %0, [%1];" : "=l"(v) : "l"(p));
    return v;
}
__device__ __forceinline__ void strelax64(unsigned long long* p, unsigned long long v) {
    asm volatile("st.relaxed.gpu.global.u64 [%0], %1;" :: "l"(p), "l"(v) : "memory");
}
__device__ __forceinline__ unsigned ldacq32(const unsigned* p) {
    unsigned v;
    asm volatile("ld.acquire.gpu.global.u32 %0, [%1];" : "=r"(v) : "l"(p));
    return v;
}
__device__ __forceinline__ void strelax32(unsigned* p, unsigned v) {
    asm volatile("st.relaxed.gpu.global.u32 [%0], %1;" :: "l"(p), "r"(v) : "memory");
}

// ================= gemm worker: one 128x128x1024 tile of xg ====================
// xg = inputs @ W_ih^T + (b_ih + b_hh). A row-major [M,K], B row-major [N,K].
__device__ void gemm_tile(const float* __restrict__ A, const float* __restrict__ B,
                          const float* __restrict__ b1, const float* __restrict__ b2,
                          int bx, int by,
                          float (*As)[132], float (*Bs)[132])
{
    const int tid = threadIdx.x;
    const int tx = tid & 15, ty = tid >> 4;
    const int rowA = by * 128;
    const int rowB = bx * 128;

    unsigned long long acc2[8][4];
#pragma unroll
    for (int i = 0; i < 8; i++)
#pragma unroll
        for (int j4 = 0; j4 < 4; j4++) acc2[i][j4] = 0ull;

    for (int kt = 0; kt < DIM; kt += 16) {
#pragma unroll
        for (int s = 0; s < 2; s++) {
            int f = tid + 256 * s;
            int r = f >> 2;
            int kq = (f & 3) * 4;
            float4 va = *(const float4*)&A[(size_t)(rowA + r) * DIM + kt + kq];
            As[kq + 0][r] = va.x; As[kq + 1][r] = va.y;
            As[kq + 2][r] = va.z; As[kq + 3][r] = va.w;
            float4 vb = *(const float4*)&B[(size_t)(rowB + r) * DIM + kt + kq];
            Bs[kq + 0][r] = vb.x; Bs[kq + 1][r] = vb.y;
            Bs[kq + 2][r] = vb.z; Bs[kq + 3][r] = vb.w;
        }
        __syncthreads();
#pragma unroll
        for (int k = 0; k < 16; k++) {
            float ar[8];
            *(float4*)(ar)     = *(const float4*)&As[k][ty * 8];
            *(float4*)(ar + 4) = *(const float4*)&As[k][ty * 8 + 4];
            float4 b0 = *(const float4*)&Bs[k][tx * 8];
            float4 b1v = *(const float4*)&Bs[k][tx * 8 + 4];
            unsigned long long br2[4];
            br2[0] = packf2(b0.x, b0.y);
            br2[1] = packf2(b0.z, b0.w);
            br2[2] = packf2(b1v.x, b1v.y);
            br2[3] = packf2(b1v.z, b1v.w);
#pragma unroll
            for (int i = 0; i < 8; i++) {
                unsigned long long ai2 = packf2(ar[i], ar[i]);
#pragma unroll
                for (int j4 = 0; j4 < 4; j4++)
                    acc2[i][j4] = fma2(ai2, br2[j4], acc2[i][j4]);
            }
        }
        __syncthreads();
    }

    float bb[8];
#pragma unroll
    for (int jj = 0; jj < 8; jj++) {
        int col = rowB + tx * 8 + jj;
        bb[jj] = b1[col] + b2[col];
    }
#pragma unroll
    for (int i = 0; i < 8; i++) {
        int row = rowA + ty * 8 + i;
        float4 o0, o1;
        o0.x = lo_f(acc2[i][0]) + bb[0];
        o0.y = hi_f(acc2[i][0]) + bb[1];
        o0.z = lo_f(acc2[i][1]) + bb[2];
        o0.w = hi_f(acc2[i][1]) + bb[3];
        o1.x = lo_f(acc2[i][2]) + bb[4];
        o1.y = hi_f(acc2[i][2]) + bb[5];
        o1.z = lo_f(acc2[i][3]) + bb[6];
        o1.w = hi_f(acc2[i][3]) + bb[7];
        *(float4*)&g_xg[(size_t)row * G4 + rowB + tx * 8]     = o0;
        *(float4*)&g_xg[(size_t)row * G4 + rowB + tx * 8 + 4] = o1;
    }
}

// ================= fused kernel: 128 lstm CTAs + 20 persistent gemm CTAs ========
// grid = 148 CTAs x 256 threads, 1 CTA/SM (all resident -> no deadlock).
// CTAs [0,128): lstm with tagged-word exchange, single-batch spin poll (proven).
// CTAs [128,148): sweep the 4096 gemm tiles in rowblock-major order; after the
// 32nd tile of a rowblock, publish flag[by] = completion count (monotone,
// replay-safe: lstm in epoch E waits for flag >= E+1).
__global__ void __launch_bounds__(256, 1) fused_kernel(
    const float* __restrict__ A,    const float* __restrict__ Bw,
    const float* __restrict__ b1,   const float* __restrict__ b2,
    const float* __restrict__ Whh)
{
    __shared__ __align__(16) float smem_a[16][132];
    __shared__ __align__(16) float smem_b[16][132];

    const int tid = threadIdx.x;

    if (blockIdx.x >= NLSTM) {
        // ---------------- persistent gemm worker ----------------
        const int w0 = blockIdx.x - NLSTM;
        for (int tt = w0; tt < 4096; tt += NGEMM) {
            const int by = tt >> 5;       // rowblock-major: all bx of by first
            const int bx = tt & 31;
            gemm_tile(A, Bw, b1, b2, bx, by, smem_a, smem_b);
            __threadfence();              // data visible before the arrival
            __syncthreads();
            if (tid == 0) {
                unsigned old = atomicAdd(&g_xgcnt[by], 1u);
                if ((old & 31u) == 31u)           // 32nd tile of this rowblock
                    strelax32(&g_xgflag[by], (old >> 5) + 1u);
            }
        }
        return;
    }

    // ---------------- lstm CTA (round-10 proven body) ----------------
    float* sh = (float*)smem_a;           // 1024 floats fit in smem_a

    const int warp = tid >> 5;
    const int lane = tid & 31;
    const int j    = blockIdx.x * 8 + warp;
    const unsigned epoch   = *(volatile unsigned*)&g_epoch;
    const unsigned tagbase = epoch * (unsigned)S_LEN;

    // preload this warp's 4 gate rows of W_hh as packed f32x2 (128 regs/thread)
    unsigned long long W0[16], W1[16], W2[16], W3[16];
#pragma unroll
    for (int m = 0; m < 16; m++) {
        int kk = m * 64 + 2 * lane;
        float2 v0 = __ldg((const float2*)&Whh[((size_t)(0 * HID + j)) * HID + kk]);
        float2 v1 = __ldg((const float2*)&Whh[((size_t)(1 * HID + j)) * HID + kk]);
        float2 v2 = __ldg((const float2*)&Whh[((size_t)(2 * HID + j)) * HID + kk]);
        float2 v3 = __ldg((const float2*)&Whh[((size_t)(3 * HID + j)) * HID + kk]);
        W0[m] = packf2(v0.x, v0.y);
        W1[m] = packf2(v1.x, v1.y);
        W2[m] = packf2(v2.x, v2.y);
        W3[m] = packf2(v3.x, v3.y);
    }

    for (int i = tid; i < HID; i += 256) sh[i] = 0.0f;   // h_{-1} = 0
    float c = 0.0f;
    __syncthreads();

    for (int t = 0; t < S_LEN; t++) {
        // gate on xg rowblock availability (1 poll thread -> no read storm)
        if ((t & 127) == 0) {
            if (tid == 0) {
                const unsigned wantf = epoch + 1u;
                while (ldacq32(&g_xgflag[t >> 7]) < wantf) { }
            }
            __syncthreads();
        }

        // prefetch the 4 xg gate values (issued early, consumed at gate stage)
        float xv = 0.0f;
        if (lane < 4) xv = __ldcg(&g_xg[(size_t)t * G4 + lane * HID + j]);

        if (t > 0) {
            // consume h[t-1]: 4 independent relaxed-atomic spin loads (MLP=4)
            const unsigned want = tagbase + (unsigned)t;   // tag of step t-1
            const unsigned long long* base = g_hpub + (size_t)(t - 1) * HID + tid;
            unsigned long long v0, v1, v2, v3;
            for (;;) {
                v0 = ldrelax64(base);
                v1 = ldrelax64(base + 256);
                v2 = ldrelax64(base + 512);
                v3 = ldrelax64(base + 768);
                bool ok = ((unsigned)(v0 >> 32) == want) &
                          ((unsigned)(v1 >> 32) == want) &
                          ((unsigned)(v2 >> 32) == want) &
                          ((unsigned)(v3 >> 32) == want);
                if (ok) break;
            }
            sh[tid]       = lo_f(v0);
            sh[tid + 256] = lo_f(v1);
            sh[tid + 512] = lo_f(v2);
            sh[tid + 768] = lo_f(v3);
        }
        __syncthreads();

        unsigned long long a0 = 0ull, a1 = 0ull, a2 = 0ull, a3 = 0ull;
#pragma unroll
        for (int m = 0; m < 16; m++) {
            unsigned long long hv = *(const unsigned long long*)&sh[m * 64 + 2 * lane];
            a0 = fma2(W0[m], hv, a0);
            a1 = fma2(W1[m], hv, a1);
            a2 = fma2(W2[m], hv, a2);
            a3 = fma2(W3[m], hv, a3);
        }
        float s0 = lo_f(a0) + hi_f(a0);
        float s1 = lo_f(a1) + hi_f(a1);
        float s2 = lo_f(a2) + hi_f(a2);
        float s3 = lo_f(a3) + hi_f(a3);
#pragma unroll
        for (int off = 16; off; off >>= 1) {
            s0 += __shfl_xor_sync(0xffffffffu, s0, off);
            s1 += __shfl_xor_sync(0xffffffffu, s1, off);
            s2 += __shfl_xor_sync(0xffffffffu, s2, off);
            s3 += __shfl_xor_sync(0xffffffffu, s3, off);
        }

        // lanes 0..3 apply their gate's nonlinearity in parallel
        float sv = (lane == 0) ? s0 : (lane == 1) ? s1 : (lane == 2) ? s2 : s3;
        float g  = (lane == 2) ? ftanh(sv + xv) : fsigmoid(sv + xv);
        float gi = __shfl_sync(0xffffffffu, g, 0);
        float gf = __shfl_sync(0xffffffffu, g, 1);
        float gc = __shfl_sync(0xffffffffu, g, 2);
        float go = __shfl_sync(0xffffffffu, g, 3);

        c = gf * c + gi * gc;               // replicated across lanes (deterministic)
        float h = go * ftanh(c);
        if (lane == 0) {
            unsigned long long w =
                ((unsigned long long)(tagbase + (unsigned)t + 1u) << 32) |
                (unsigned long long)__float_as_uint(h);
            strelax64(g_hpub + (size_t)t * HID + j, w);
        }
        __syncthreads();   // park all warps while publishes drain (protective)
    }
}

// ================= Phase 3: alpha = sigmoid(h @ W_fc^T + b_fc) =================
__global__ void __launch_bounds__(256) alpha_kernel(const float* __restrict__ Wfc,
                                                    const float* __restrict__ bfc)
{
    const int lane = threadIdx.x & 31;
    const int t = blockIdx.x * 8 + (threadIdx.x >> 5);
    const unsigned long long* hp = g_hpub + (size_t)t * HID;
    float acc = 0.0f;
#pragma unroll
    for (int i = 0; i < 32; i++) {
        unsigned long long w = __ldcg(&hp[i * 32 + lane]);
        acc += lo_f(w) * __ldg(&Wfc[i * 32 + lane]);
    }
#pragma unroll
    for (int off = 16; off; off >>= 1)
        acc += __shfl_xor_sync(0xffffffffu, acc, off);
    if (lane == 0)
        g_alpha[t] = fsigmoid(acc + __ldg(bfc));
}

// ================= Phase 4: parallel scans for gated recurrence + loss ===========
// out layout: [0]=loss, [1..N]=y_seq, [1+N..1+2N)=a_seq, [1+2N..1+3N)=u,  N=16383
__global__ void __launch_bounds__(1024) final_kernel(const float* __restrict__ up,
                                                     const float* __restrict__ tl,
                                                     float* __restrict__ out)
{
    const int N = S_LEN - 1;
    __shared__ float sA[1024], sB[1024];
    __shared__ int s_idx;
    const int tid = threadIdx.x;
    const int base = tid * 16;

    if (tid == 0) s_idx = 0x7fffffff;
    __syncthreads();
    {
        int my = 0x7fffffff;
#pragma unroll
        for (int k = 0; k < 16; k++) {
            int i = base + k;
            if (i < N && tl[i] > 0.8f) { my = i; break; }
        }
        if (my != 0x7fffffff) atomicMin(&s_idx, my);
    }

    // ---- local compose of a-recurrence affine maps
    float A = 1.f, B = 0.f;
#pragma unroll
    for (int k = 0; k < 16; k++) {
        int i = base + k;
        float u  = (i < N) ? 1.0f - up[i + 1] : 1.0f;
        float ai = (i < N) ? g_alpha[i + 1]   : 0.0f;
        float Ak = u, Bk = (1.0f - u) * ai;
        B = Ak * B + Bk;
        A = Ak * A;
    }
    sA[tid] = A; sB[tid] = B;
    __syncthreads();
    for (int off = 1; off < 1024; off <<= 1) {
        float aL = 0.f, bL = 0.f;
        if (tid >= off) { aL = sA[tid - off]; bL = sB[tid - off]; }
        float aC = sA[tid], bC = sB[tid];
        __syncthreads();
        if (tid >= off) { sA[tid] = aC * aL; sB[tid] = aC * bL + bC; }
        __syncthreads();
    }
    const float a_prev0 = (tid == 0) ? 0.f : sB[tid - 1];
    __syncthreads();

    // ---- emit a_seq/u, compose y-recurrence maps
    float C = 1.f, D = 0.f;
    {
        float ap = a_prev0;
#pragma unroll
        for (int k = 0; k < 16; k++) {
            int i = base + k;
            float u  = (i < N) ? 1.0f - up[i + 1] : 1.0f;
            float ai = (i < N) ? g_alpha[i + 1]   : 0.0f;
            float ag = u * ap + (1.0f - u) * ai;
            ap = ag;
            if (i < N) {
                out[1 + N + i]     = ag;
                out[1 + 2 * N + i] = u;
                float Ck = 1.0f - ag, Dk = ag * u;
                D = Ck * D + Dk;
                C = Ck * C;
            }
        }
    }
    sA[tid] = C; sB[tid] = D;
    __syncthreads();
    for (int off = 1; off < 1024; off <<= 1) {
        float aL = 0.f, bL = 0.f;
        if (tid >= off) { aL = sA[tid - off]; bL = sB[tid - off]; }
        float aC = sA[tid], bC = sB[tid];
        __syncthreads();
        if (tid >= off) { sA[tid] = aC * aL; sB[tid] = aC * bL + bC; }
        __syncthreads();
    }
    const float y_prev0 = (tid == 0) ? 0.f : sB[tid - 1];

    // ---- emit y_seq
    {
        float ap = a_prev0, yp = y_prev0;
#pragma unroll
        for (int k = 0; k < 16; k++) {
            int i = base + k;
            float u  = (i < N) ? 1.0f - up[i + 1] : 1.0f;
            float ai = (i < N) ? g_alpha[i + 1]   : 0.0f;
            float ag = u * ap + (1.0f - u) * ai;
            ap = ag;
            if (i < N) {
                float y = ag * u + (1.0f - ag) * yp;
                yp = y;
                out[1 + i] = y;
            }
        }
    }
    __syncthreads();

    if (tid == 0) {
        int idx = s_idx;
        bool exists = (idx != 0x7fffffff);
        float loss;
        if (exists) {
            float u_at = 1.0f - up[idx + 1];
            float y_at = out[1 + idx];
            loss = (u_at < 0.5f) ? 0.0f : (y_at - 0.8f) * (y_at - 0.8f);
        } else {
            float yl = out[1 + N - 1];
            loss = (yl >= 0.8f) ? (yl - 0.4f) * (yl - 0.4f) : 0.0f;
        }
        out[0] = loss;
    }
}

// ================= epoch bump (replay-safe monotone tags) =================
__global__ void bump_kernel() { g_epoch = g_epoch + 1u; }

// ================= launch =================
extern "C" void kernel_launch(void* const* d_in, const int* in_sizes, int n_in,
                              void* d_out, int out_size)
{
    const float* inputs    = (const float*)d_in[0];
    const float* uttr_pred = (const float*)d_in[1];
    const float* timing    = (const float*)d_in[2];
    /* d_in[3] uttr_label unused */
    const float* W_ih = (const float*)d_in[4];
    const float* W_hh = (const float*)d_in[5];
    const float* b_ih = (const float*)d_in[6];
    const float* b_hh = (const float*)d_in[7];
    const float* W_fc = (const float*)d_in[8];
    const float* b_fc = (const float*)d_in[9];
    float* out = (float*)d_out;

    fused_kernel<<<NLSTM + NGEMM, 256>>>(inputs, W_ih, b_ih, b_hh, W_hh);
    alpha_kernel<<<S_LEN / 8, 256>>>(W_fc, b_fc);
    final_kernel<<<1, 1024>>>(uttr_pred, timing, out);
    bump_kernel<<<1, 1>>>();
}

// round 14
// speedup vs baseline: 1.6528x; 1.6528x over previous
#include <cuda_runtime.h>
#include <math.h>

#define S_LEN 16384
#define DIM   1024
#define HID   1024
#define G4    4096   // 4*HID
#define NLSTM 128    // lstm CTAs (1/SM)
#define NGEMM 20     // persistent gemm worker CTAs (separate SMs)

// ---------------- scratch (no allocations allowed) ----------------
__device__ float g_xg[(size_t)S_LEN * G4];                  // 256 MB: input gates
__device__ unsigned long long g_hpub[(size_t)S_LEN * HID];  // 128 MB: (tag<<32)|h
__device__ float g_alpha[S_LEN];
__device__ unsigned g_epoch;                                // bumped once per launch
__device__ unsigned g_xgcnt[128];                           // per-rowblock tile count
__device__ unsigned g_xgflag[128];                          // rowblock completion count

// ---------------- helpers ----------------
__device__ __forceinline__ float fsigmoid(float x) {
    return __fdividef(1.0f, 1.0f + __expf(-x));
}
__device__ __forceinline__ float ftanh(float x) {
    float e = __expf(2.0f * x);
    return 1.0f - __fdividef(2.0f, e + 1.0f);
}
__device__ __forceinline__ unsigned long long fma2(unsigned long long a,
                                                   unsigned long long b,
                                                   unsigned long long c) {
    unsigned long long d;
    asm("fma.rn.f32x2 %0, %1, %2, %3;" : "=l"(d) : "l"(a), "l"(b), "l"(c));
    return d;
}
__device__ __forceinline__ unsigned long long packf2(float x, float y) {
    unsigned long long d;
    asm("mov.b64 %0, {%1, %2};" : "=l"(d) : "f"(x), "f"(y));
    return d;
}
__device__ __forceinline__ float lo_f(unsigned long long v) {
    return __uint_as_float((unsigned)v);
}
__device__ __forceinline__ float hi_f(unsigned long long v) {
    return __uint_as_float((unsigned)(v >> 32));
}
__device__ __forceinline__ unsigned long long ldrelax64(const unsigned long long* p) {
    unsigned long long v;
    asm volatile("ld.relaxed.gpu.global.u64 %0, [%1];" : "=l"(v) : "l"(p));
    return v;
}
__device__ __forceinline__ void strelax64(unsigned long long* p, unsigned long long v) {
    asm volatile("st.relaxed.gpu.global.u64 [%0], %1;" :: "l"(p), "l"(v) : "memory");
}
__device__ __forceinline__ unsigned ldacq32(const unsigned* p) {
    unsigned v;
    asm volatile("ld.acquire.gpu.global.u32 %0, [%1];" : "=r"(v) : "l"(p));
    return v;
}
__device__ __forceinline__ void strelax32(unsigned* p, unsigned v) {
    asm volatile("st.relaxed.gpu.global.u32 [%0], %1;" :: "l"(p), "r"(v) : "memory");
}

// ================= gemm worker: one 128x128x1024 tile of xg ====================
// xg = inputs @ W_ih^T + (b_ih + b_hh). A row-major [M,K], B row-major [N,K].
__device__ void gemm_tile(const float* __restrict__ A, const float* __restrict__ B,
                          const float* __restrict__ b1, const float* __restrict__ b2,
                          int bx, int by,
                          float (*As)[132], float (*Bs)[132])
{
    const int tid = threadIdx.x;
    const int tx = tid & 15, ty = tid >> 4;
    const int rowA = by * 128;
    const int rowB = bx * 128;

    unsigned long long acc2[8][4];
#pragma unroll
    for (int i = 0; i < 8; i++)
#pragma unroll
        for (int j4 = 0; j4 < 4; j4++) acc2[i][j4] = 0ull;

    for (int kt = 0; kt < DIM; kt += 16) {
#pragma unroll
        for (int s = 0; s < 2; s++) {
            int f = tid + 256 * s;
            int r = f >> 2;
            int kq = (f & 3) * 4;
            float4 va = *(const float4*)&A[(size_t)(rowA + r) * DIM + kt + kq];
            As[kq + 0][r] = va.x; As[kq + 1][r] = va.y;
            As[kq + 2][r] = va.z; As[kq + 3][r] = va.w;
            float4 vb = *(const float4*)&B[(size_t)(rowB + r) * DIM + kt + kq];
            Bs[kq + 0][r] = vb.x; Bs[kq + 1][r] = vb.y;
            Bs[kq + 2][r] = vb.z; Bs[kq + 3][r] = vb.w;
        }
        __syncthreads();
#pragma unroll
        for (int k = 0; k < 16; k++) {
            float ar[8];
            *(float4*)(ar)     = *(const float4*)&As[k][ty * 8];
            *(float4*)(ar + 4) = *(const float4*)&As[k][ty * 8 + 4];
            float4 b0 = *(const float4*)&Bs[k][tx * 8];
            float4 b1v = *(const float4*)&Bs[k][tx * 8 + 4];
            unsigned long long br2[4];
            br2[0] = packf2(b0.x, b0.y);
            br2[1] = packf2(b0.z, b0.w);
            br2[2] = packf2(b1v.x, b1v.y);
            br2[3] = packf2(b1v.z, b1v.w);
#pragma unroll
            for (int i = 0; i < 8; i++) {
                unsigned long long ai2 = packf2(ar[i], ar[i]);
#pragma unroll
                for (int j4 = 0; j4 < 4; j4++)
                    acc2[i][j4] = fma2(ai2, br2[j4], acc2[i][j4]);
            }
        }
        __syncthreads();
    }

    float bb[8];
#pragma unroll
    for (int jj = 0; jj < 8; jj++) {
        int col = rowB + tx * 8 + jj;
        bb[jj] = b1[col] + b2[col];
    }
#pragma unroll
    for (int i = 0; i < 8; i++) {
        int row = rowA + ty * 8 + i;
        float4 o0, o1;
        o0.x = lo_f(acc2[i][0]) + bb[0];
        o0.y = hi_f(acc2[i][0]) + bb[1];
        o0.z = lo_f(acc2[i][1]) + bb[2];
        o0.w = hi_f(acc2[i][1]) + bb[3];
        o1.x = lo_f(acc2[i][2]) + bb[4];
        o1.y = hi_f(acc2[i][2]) + bb[5];
        o1.z = lo_f(acc2[i][3]) + bb[6];
        o1.w = hi_f(acc2[i][3]) + bb[7];
        *(float4*)&g_xg[(size_t)row * G4 + rowB + tx * 8]     = o0;
        *(float4*)&g_xg[(size_t)row * G4 + rowB + tx * 8 + 4] = o1;
    }
}

// ================= fused kernel: 128 lstm CTAs + 20 persistent gemm CTAs ========
// grid = 148 CTAs x 256 threads, 1 CTA/SM (all resident -> no deadlock).
// CTAs [0,128): lstm with tagged-word exchange; publish is COALESCED: each warp
// stages h in smem, then warp 0 lanes 0-7 emit the CTA's 8 tagged words as one
// 64B store wavefront (1 L2 transaction instead of 8 same-sector RMWs).
// CTAs [128,148): sweep the 4096 gemm tiles in rowblock-major order.
__global__ void __launch_bounds__(256, 1) fused_kernel(
    const float* __restrict__ A,    const float* __restrict__ Bw,
    const float* __restrict__ b1,   const float* __restrict__ b2,
    const float* __restrict__ Whh)
{
    __shared__ __align__(16) float smem_a[16][132];
    __shared__ __align__(16) float smem_b[16][132];
    __shared__ float sh_out[8];           // per-warp h staging (lstm CTAs only)

    const int tid = threadIdx.x;

    if (blockIdx.x >= NLSTM) {
        // ---------------- persistent gemm worker ----------------
        const int w0 = blockIdx.x - NLSTM;
        for (int tt = w0; tt < 4096; tt += NGEMM) {
            const int by = tt >> 5;       // rowblock-major: all bx of by first
            const int bx = tt & 31;
            gemm_tile(A, Bw, b1, b2, bx, by, smem_a, smem_b);
            __threadfence();              // data visible before the arrival
            __syncthreads();
            if (tid == 0) {
                unsigned old = atomicAdd(&g_xgcnt[by], 1u);
                if ((old & 31u) == 31u)           // 32nd tile of this rowblock
                    strelax32(&g_xgflag[by], (old >> 5) + 1u);
            }
        }
        return;
    }

    // ---------------- lstm CTA ----------------
    float* sh = (float*)smem_a;           // 1024 floats fit in smem_a

    const int warp = tid >> 5;
    const int lane = tid & 31;
    const int j    = blockIdx.x * 8 + warp;
    const unsigned epoch   = *(volatile unsigned*)&g_epoch;
    const unsigned tagbase = epoch * (unsigned)S_LEN;

    // preload this warp's 4 gate rows of W_hh as packed f32x2 (128 regs/thread)
    unsigned long long W0[16], W1[16], W2[16], W3[16];
#pragma unroll
    for (int m = 0; m < 16; m++) {
        int kk = m * 64 + 2 * lane;
        float2 v0 = __ldg((const float2*)&Whh[((size_t)(0 * HID + j)) * HID + kk]);
        float2 v1 = __ldg((const float2*)&Whh[((size_t)(1 * HID + j)) * HID + kk]);
        float2 v2 = __ldg((const float2*)&Whh[((size_t)(2 * HID + j)) * HID + kk]);
        float2 v3 = __ldg((const float2*)&Whh[((size_t)(3 * HID + j)) * HID + kk]);
        W0[m] = packf2(v0.x, v0.y);
        W1[m] = packf2(v1.x, v1.y);
        W2[m] = packf2(v2.x, v2.y);
        W3[m] = packf2(v3.x, v3.y);
    }

    for (int i = tid; i < HID; i += 256) sh[i] = 0.0f;   // h_{-1} = 0
    float c = 0.0f;
    __syncthreads();

    for (int t = 0; t < S_LEN; t++) {
        // gate on xg rowblock availability (1 poll thread -> no read storm)
        if ((t & 127) == 0) {
            if (tid == 0) {
                const unsigned wantf = epoch + 1u;
                while (ldacq32(&g_xgflag[t >> 7]) < wantf) { }
            }
            __syncthreads();
        }

        // prefetch the 4 xg gate values (issued early, consumed at gate stage)
        float xv = 0.0f;
        if (lane < 4) xv = __ldcg(&g_xg[(size_t)t * G4 + lane * HID + j]);

        if (t > 0) {
            // consume h[t-1]: 4 independent relaxed-atomic spin loads (MLP=4)
            const unsigned want = tagbase + (unsigned)t;   // tag of step t-1
            const unsigned long long* base = g_hpub + (size_t)(t - 1) * HID + tid;
            unsigned long long v0, v1, v2, v3;
            for (;;) {
                v0 = ldrelax64(base);
                v1 = ldrelax64(base + 256);
                v2 = ldrelax64(base + 512);
                v3 = ldrelax64(base + 768);
                bool ok = ((unsigned)(v0 >> 32) == want) &
                          ((unsigned)(v1 >> 32) == want) &
                          ((unsigned)(v2 >> 32) == want) &
                          ((unsigned)(v3 >> 32) == want);
                if (ok) break;
            }
            sh[tid]       = lo_f(v0);
            sh[tid + 256] = lo_f(v1);
            sh[tid + 512] = lo_f(v2);
            sh[tid + 768] = lo_f(v3);
        }
        __syncthreads();

        unsigned long long a0 = 0ull, a1 = 0ull, a2 = 0ull, a3 = 0ull;
#pragma unroll
        for (int m = 0; m < 16; m++) {
            unsigned long long hv = *(const unsigned long long*)&sh[m * 64 + 2 * lane];
            a0 = fma2(W0[m], hv, a0);
            a1 = fma2(W1[m], hv, a1);
            a2 = fma2(W2[m], hv, a2);
            a3 = fma2(W3[m], hv, a3);
        }
        float s0 = lo_f(a0) + hi_f(a0);
        float s1 = lo_f(a1) + hi_f(a1);
        float s2 = lo_f(a2) + hi_f(a2);
        float s3 = lo_f(a3) + hi_f(a3);
#pragma unroll
        for (int off = 16; off; off >>= 1) {
            s0 += __shfl_xor_sync(0xffffffffu, s0, off);
            s1 += __shfl_xor_sync(0xffffffffu, s1, off);
            s2 += __shfl_xor_sync(0xffffffffu, s2, off);
            s3 += __shfl_xor_sync(0xffffffffu, s3, off);
        }

        // lanes 0..3 apply their gate's nonlinearity in parallel
        float sv = (lane == 0) ? s0 : (lane == 1) ? s1 : (lane == 2) ? s2 : s3;
        float g  = (lane == 2) ? ftanh(sv + xv) : fsigmoid(sv + xv);
        float gi = __shfl_sync(0xffffffffu, g, 0);
        float gf = __shfl_sync(0xffffffffu, g, 1);
        float gc = __shfl_sync(0xffffffffu, g, 2);
        float go = __shfl_sync(0xffffffffu, g, 3);

        c = gf * c + gi * gc;               // replicated across lanes (deterministic)
        float h = go * ftanh(c);
        if (lane == 0) sh_out[warp] = h;    // stage this warp's h
        __syncthreads();                    // h staged; also parks warps (protective)
        if (warp == 0 && lane < 8) {
            // one coalesced 64B publish wavefront for the whole CTA
            unsigned long long w =
                ((unsigned long long)(tagbase + (unsigned)t + 1u) << 32) |
                (unsigned long long)__float_as_uint(sh_out[lane]);
            strelax64(g_hpub + (size_t)t * HID + blockIdx.x * 8 + lane, w);
        }
    }
}

// ================= Phase 3: alpha = sigmoid(h @ W_fc^T + b_fc) =================
__global__ void __launch_bounds__(256) alpha_kernel(const float* __restrict__ Wfc,
                                                    const float* __restrict__ bfc)
{
    const int lane = threadIdx.x & 31;
    const int t = blockIdx.x * 8 + (threadIdx.x >> 5);
    const unsigned long long* hp = g_hpub + (size_t)t * HID;
    float acc = 0.0f;
#pragma unroll
    for (int i = 0; i < 32; i++) {
        unsigned long long w = __ldcg(&hp[i * 32 + lane]);
        acc += lo_f(w) * __ldg(&Wfc[i * 32 + lane]);
    }
#pragma unroll
    for (int off = 16; off; off >>= 1)
        acc += __shfl_xor_sync(0xffffffffu, acc, off);
    if (lane == 0)
        g_alpha[t] = fsigmoid(acc + __ldg(bfc));
}

// ================= Phase 4: parallel scans for gated recurrence + loss ===========
// out layout: [0]=loss, [1..N]=y_seq, [1+N..1+2N)=a_seq, [1+2N..1+3N)=u,  N=16383
__global__ void __launch_bounds__(1024) final_kernel(const float* __restrict__ up,
                                                     const float* __restrict__ tl,
                                                     float* __restrict__ out)
{
    const int N = S_LEN - 1;
    __shared__ float sA[1024], sB[1024];
    __shared__ int s_idx;
    const int tid = threadIdx.x;
    const int base = tid * 16;

    if (tid == 0) s_idx = 0x7fffffff;
    __syncthreads();
    {
        int my = 0x7fffffff;
#pragma unroll
        for (int k = 0; k < 16; k++) {
            int i = base + k;
            if (i < N && tl[i] > 0.8f) { my = i; break; }
        }
        if (my != 0x7fffffff) atomicMin(&s_idx, my);
    }

    // ---- local compose of a-recurrence affine maps
    float A = 1.f, B = 0.f;
#pragma unroll
    for (int k = 0; k < 16; k++) {
        int i = base + k;
        float u  = (i < N) ? 1.0f - up[i + 1] : 1.0f;
        float ai = (i < N) ? g_alpha[i + 1]   : 0.0f;
        float Ak = u, Bk = (1.0f - u) * ai;
        B = Ak * B + Bk;
        A = Ak * A;
    }
    sA[tid] = A; sB[tid] = B;
    __syncthreads();
    for (int off = 1; off < 1024; off <<= 1) {
        float aL = 0.f, bL = 0.f;
        if (tid >= off) { aL = sA[tid - off]; bL = sB[tid - off]; }
        float aC = sA[tid], bC = sB[tid];
        __syncthreads();
        if (tid >= off) { sA[tid] = aC * aL; sB[tid] = aC * bL + bC; }
        __syncthreads();
    }
    const float a_prev0 = (tid == 0) ? 0.f : sB[tid - 1];
    __syncthreads();

    // ---- emit a_seq/u, compose y-recurrence maps
    float C = 1.f, D = 0.f;
    {
        float ap = a_prev0;
#pragma unroll
        for (int k = 0; k < 16; k++) {
            int i = base + k;
            float u  = (i < N) ? 1.0f - up[i + 1] : 1.0f;
            float ai = (i < N) ? g_alpha[i + 1]   : 0.0f;
            float ag = u * ap + (1.0f - u) * ai;
            ap = ag;
            if (i < N) {
                out[1 + N + i]     = ag;
                out[1 + 2 * N + i] = u;
                float Ck = 1.0f - ag, Dk = ag * u;
                D = Ck * D + Dk;
                C = Ck * C;
            }
        }
    }
    sA[tid] = C; sB[tid] = D;
    __syncthreads();
    for (int off = 1; off < 1024; off <<= 1) {
        float aL = 0.f, bL = 0.f;
        if (tid >= off) { aL = sA[tid - off]; bL = sB[tid - off]; }
        float aC = sA[tid], bC = sB[tid];
        __syncthreads();
        if (tid >= off) { sA[tid] = aC * aL; sB[tid] = aC * bL + bC; }
        __syncthreads();
    }
    const float y_prev0 = (tid == 0) ? 0.f : sB[tid - 1];

    // ---- emit y_seq
    {
        float ap = a_prev0, yp = y_prev0;
#pragma unroll
        for (int k = 0; k < 16; k++) {
            int i = base + k;
            float u  = (i < N) ? 1.0f - up[i + 1] : 1.0f;
            float ai = (i < N) ? g_alpha[i + 1]   : 0.0f;
            float ag = u * ap + (1.0f - u) * ai;
            ap = ag;
            if (i < N) {
                float y = ag * u + (1.0f - ag) * yp;
                yp = y;
                out[1 + i] = y;
            }
        }
    }
    __syncthreads();

    if (tid == 0) {
        int idx = s_idx;
        bool exists = (idx != 0x7fffffff);
        float loss;
        if (exists) {
            float u_at = 1.0f - up[idx + 1];
            float y_at = out[1 + idx];
            loss = (u_at < 0.5f) ? 0.0f : (y_at - 0.8f) * (y_at - 0.8f);
        } else {
            float yl = out[1 + N - 1];
            loss = (yl >= 0.8f) ? (yl - 0.4f) * (yl - 0.4f) : 0.0f;
        }
        out[0] = loss;
    }
}

// ================= epoch bump (replay-safe monotone tags) =================
__global__ void bump_kernel() { g_epoch = g_epoch + 1u; }

// ================= launch =================
extern "C" void kernel_launch(void* const* d_in, const int* in_sizes, int n_in,
                              void* d_out, int out_size)
{
    const float* inputs    = (const float*)d_in[0];
    const float* uttr_pred = (const float*)d_in[1];
    const float* timing    = (const float*)d_in[2];
    /* d_in[3] uttr_label unused */
    const float* W_ih = (const float*)d_in[4];
    const float* W_hh = (const float*)d_in[5];
    const float* b_ih = (const float*)d_in[6];
    const float* b_hh = (const float*)d_in[7];
    const float* W_fc = (const float*)d_in[8];
    const float* b_fc = (const float*)d_in[9];
    float* out = (float*)d_out;

    fused_kernel<<<NLSTM + NGEMM, 256>>>(inputs, W_ih, b_ih, b_hh, W_hh);
    alpha_kernel<<<S_LEN / 8, 256>>>(W_fc, b_fc);
    final_kernel<<<1, 1024>>>(uttr_pred, timing, out);
    bump_kernel<<<1, 1>>>();
}

// round 15
// speedup vs baseline: 1.6572x; 1.0027x over previous
#include <cuda_runtime.h>
#include <math.h>

#define S_LEN 16384
#define DIM   1024
#define HID   1024
#define G4    4096   // 4*HID
#define NLSTM 128    // lstm CTAs (1/SM)
#define NGEMM 20     // persistent gemm worker CTAs (separate SMs)

// ---------------- scratch (no allocations allowed) ----------------
__device__ float g_xg[(size_t)S_LEN * G4];                  // 256 MB: input gates
__device__ unsigned long long g_hpub[(size_t)S_LEN * HID];  // 128 MB: (tag<<32)|h
__device__ float g_alpha[S_LEN];
__device__ unsigned g_epoch;                                // bumped once per launch
__device__ unsigned g_xgcnt[128];                           // per-rowblock tile count
__device__ unsigned g_xgflag[128];                          // rowblock completion count

// ---------------- helpers ----------------
__device__ __forceinline__ float fsigmoid(float x) {
    return __fdividef(1.0f, 1.0f + __expf(-x));
}
__device__ __forceinline__ float ftanh(float x) {
    float e = __expf(2.0f * x);
    return 1.0f - __fdividef(2.0f, e + 1.0f);
}
__device__ __forceinline__ unsigned long long fma2(unsigned long long a,
                                                   unsigned long long b,
                                                   unsigned long long c) {
    unsigned long long d;
    asm("fma.rn.f32x2 %0, %1, %2, %3;" : "=l"(d) : "l"(a), "l"(b), "l"(c));
    return d;
}
__device__ __forceinline__ unsigned long long packf2(float x, float y) {
    unsigned long long d;
    asm("mov.b64 %0, {%1, %2};" : "=l"(d) : "f"(x), "f"(y));
    return d;
}
__device__ __forceinline__ float lo_f(unsigned long long v) {
    return __uint_as_float((unsigned)v);
}
__device__ __forceinline__ float hi_f(unsigned long long v) {
    return __uint_as_float((unsigned)(v >> 32));
}
__device__ __forceinline__ unsigned long long ldrelax64(const unsigned long long* p) {
    unsigned long long v;
    asm volatile("ld.relaxed.gpu.global.u64 %0, [%1];" : "=l"(v) : "l"(p));
    return v;
}
__device__ __forceinline__ void strelax64(unsigned long long* p, unsigned long long v) {
    asm volatile("st.relaxed.gpu.global.u64 [%0], %1;" :: "l"(p), "l"(v) : "memory");
}
__device__ __forceinline__ unsigned ldacq32(const unsigned* p) {
    unsigned v;
    asm volatile("ld.acquire.gpu.global.u32 %0, [%1];" : "=r"(v) : "l"(p));
    return v;
}
__device__ __forceinline__ void strelax32(unsigned* p, unsigned v) {
    asm volatile("st.relaxed.gpu.global.u32 [%0], %1;" :: "l"(p), "r"(v) : "memory");
}

// ================= gemm worker: one 128x128x1024 tile of xg ====================
// xg = inputs @ W_ih^T + (b_ih + b_hh). A row-major [M,K], B row-major [N,K].
__device__ void gemm_tile(const float* __restrict__ A, const float* __restrict__ B,
                          const float* __restrict__ b1, const float* __restrict__ b2,
                          int bx, int by,
                          float (*As)[132], float (*Bs)[132])
{
    const int tid = threadIdx.x;
    const int tx = tid & 15, ty = tid >> 4;
    const int rowA = by * 128;
    const int rowB = bx * 128;

    unsigned long long acc2[8][4];
#pragma unroll
    for (int i = 0; i < 8; i++)
#pragma unroll
        for (int j4 = 0; j4 < 4; j4++) acc2[i][j4] = 0ull;

    for (int kt = 0; kt < DIM; kt += 16) {
#pragma unroll
        for (int s = 0; s < 2; s++) {
            int f = tid + 256 * s;
            int r = f >> 2;
            int kq = (f & 3) * 4;
            float4 va = *(const float4*)&A[(size_t)(rowA + r) * DIM + kt + kq];
            As[kq + 0][r] = va.x; As[kq + 1][r] = va.y;
            As[kq + 2][r] = va.z; As[kq + 3][r] = va.w;
            float4 vb = *(const float4*)&B[(size_t)(rowB + r) * DIM + kt + kq];
            Bs[kq + 0][r] = vb.x; Bs[kq + 1][r] = vb.y;
            Bs[kq + 2][r] = vb.z; Bs[kq + 3][r] = vb.w;
        }
        __syncthreads();
#pragma unroll
        for (int k = 0; k < 16; k++) {
            float ar[8];
            *(float4*)(ar)     = *(const float4*)&As[k][ty * 8];
            *(float4*)(ar + 4) = *(const float4*)&As[k][ty * 8 + 4];
            float4 b0 = *(const float4*)&Bs[k][tx * 8];
            float4 b1v = *(const float4*)&Bs[k][tx * 8 + 4];
            unsigned long long br2[4];
            br2[0] = packf2(b0.x, b0.y);
            br2[1] = packf2(b0.z, b0.w);
            br2[2] = packf2(b1v.x, b1v.y);
            br2[3] = packf2(b1v.z, b1v.w);
#pragma unroll
            for (int i = 0; i < 8; i++) {
                unsigned long long ai2 = packf2(ar[i], ar[i]);
#pragma unroll
                for (int j4 = 0; j4 < 4; j4++)
                    acc2[i][j4] = fma2(ai2, br2[j4], acc2[i][j4]);
            }
        }
        __syncthreads();
    }

    float bb[8];
#pragma unroll
    for (int jj = 0; jj < 8; jj++) {
        int col = rowB + tx * 8 + jj;
        bb[jj] = b1[col] + b2[col];
    }
#pragma unroll
    for (int i = 0; i < 8; i++) {
        int row = rowA + ty * 8 + i;
        float4 o0, o1;
        o0.x = lo_f(acc2[i][0]) + bb[0];
        o0.y = hi_f(acc2[i][0]) + bb[1];
        o0.z = lo_f(acc2[i][1]) + bb[2];
        o0.w = hi_f(acc2[i][1]) + bb[3];
        o1.x = lo_f(acc2[i][2]) + bb[4];
        o1.y = hi_f(acc2[i][2]) + bb[5];
        o1.z = lo_f(acc2[i][3]) + bb[6];
        o1.w = hi_f(acc2[i][3]) + bb[7];
        *(float4*)&g_xg[(size_t)row * G4 + rowB + tx * 8]     = o0;
        *(float4*)&g_xg[(size_t)row * G4 + rowB + tx * 8 + 4] = o1;
    }
}

// ================= fused kernel: 128 lstm CTAs + 20 persistent gemm CTAs ========
// grid = 148 CTAs x 256 threads, 1 CTA/SM (all resident -> no deadlock).
// CTAs [0,128): lstm. Publish: coalesced 64B wavefront (r14 win). Consume: spin
// that re-polls ONLY incomplete words (tags monotone + written once per epoch,
// so a matched word is final) -> poll traffic decays as producers complete.
// CTAs [128,148): sweep the 4096 gemm tiles in rowblock-major order.
__global__ void __launch_bounds__(256, 1) fused_kernel(
    const float* __restrict__ A,    const float* __restrict__ Bw,
    const float* __restrict__ b1,   const float* __restrict__ b2,
    const float* __restrict__ Whh)
{
    __shared__ __align__(16) float smem_a[16][132];
    __shared__ __align__(16) float smem_b[16][132];
    __shared__ float sh_out[8];           // per-warp h staging (lstm CTAs only)

    const int tid = threadIdx.x;

    if (blockIdx.x >= NLSTM) {
        // ---------------- persistent gemm worker ----------------
        const int w0 = blockIdx.x - NLSTM;
        for (int tt = w0; tt < 4096; tt += NGEMM) {
            const int by = tt >> 5;       // rowblock-major: all bx of by first
            const int bx = tt & 31;
            gemm_tile(A, Bw, b1, b2, bx, by, smem_a, smem_b);
            __threadfence();              // data visible before the arrival
            __syncthreads();
            if (tid == 0) {
                unsigned old = atomicAdd(&g_xgcnt[by], 1u);
                if ((old & 31u) == 31u)           // 32nd tile of this rowblock
                    strelax32(&g_xgflag[by], (old >> 5) + 1u);
            }
        }
        return;
    }

    // ---------------- lstm CTA ----------------
    float* sh = (float*)smem_a;           // 1024 floats fit in smem_a

    const int warp = tid >> 5;
    const int lane = tid & 31;
    const int j    = blockIdx.x * 8 + warp;
    const unsigned epoch   = *(volatile unsigned*)&g_epoch;
    const unsigned tagbase = epoch * (unsigned)S_LEN;

    // preload this warp's 4 gate rows of W_hh as packed f32x2 (128 regs/thread)
    unsigned long long W0[16], W1[16], W2[16], W3[16];
#pragma unroll
    for (int m = 0; m < 16; m++) {
        int kk = m * 64 + 2 * lane;
        float2 v0 = __ldg((const float2*)&Whh[((size_t)(0 * HID + j)) * HID + kk]);
        float2 v1 = __ldg((const float2*)&Whh[((size_t)(1 * HID + j)) * HID + kk]);
        float2 v2 = __ldg((const float2*)&Whh[((size_t)(2 * HID + j)) * HID + kk]);
        float2 v3 = __ldg((const float2*)&Whh[((size_t)(3 * HID + j)) * HID + kk]);
        W0[m] = packf2(v0.x, v0.y);
        W1[m] = packf2(v1.x, v1.y);
        W2[m] = packf2(v2.x, v2.y);
        W3[m] = packf2(v3.x, v3.y);
    }

    for (int i = tid; i < HID; i += 256) sh[i] = 0.0f;   // h_{-1} = 0
    float c = 0.0f;
    __syncthreads();

    for (int t = 0; t < S_LEN; t++) {
        // gate on xg rowblock availability (1 poll thread -> no read storm)
        if ((t & 127) == 0) {
            if (tid == 0) {
                const unsigned wantf = epoch + 1u;
                while (ldacq32(&g_xgflag[t >> 7]) < wantf) { }
            }
            __syncthreads();
        }

        // prefetch the 4 xg gate values (issued early, consumed at gate stage)
        float xv = 0.0f;
        if (lane < 4) xv = __ldcg(&g_xg[(size_t)t * G4 + lane * HID + j]);

        if (t > 0) {
            // consume h[t-1]: spin re-polling ONLY the words still incomplete.
            // A word whose tag matches is final (monotone tag, one write/epoch),
            // so its captured value is sound and it is never re-read.
            const unsigned want = tagbase + (unsigned)t;   // tag of step t-1
            const unsigned long long* base = g_hpub + (size_t)(t - 1) * HID + tid;
            unsigned long long v0 = 0, v1 = 0, v2 = 0, v3 = 0;
            bool d0 = false, d1 = false, d2 = false, d3 = false;
            for (;;) {
                if (!d0) { v0 = ldrelax64(base);       }
                if (!d1) { v1 = ldrelax64(base + 256); }
                if (!d2) { v2 = ldrelax64(base + 512); }
                if (!d3) { v3 = ldrelax64(base + 768); }
                d0 = d0 | ((unsigned)(v0 >> 32) == want);
                d1 = d1 | ((unsigned)(v1 >> 32) == want);
                d2 = d2 | ((unsigned)(v2 >> 32) == want);
                d3 = d3 | ((unsigned)(v3 >> 32) == want);
                if (d0 & d1 & d2 & d3) break;
            }
            sh[tid]       = lo_f(v0);
            sh[tid + 256] = lo_f(v1);
            sh[tid + 512] = lo_f(v2);
            sh[tid + 768] = lo_f(v3);
        }
        __syncthreads();

        unsigned long long a0 = 0ull, a1 = 0ull, a2 = 0ull, a3 = 0ull;
#pragma unroll
        for (int m = 0; m < 16; m++) {
            unsigned long long hv = *(const unsigned long long*)&sh[m * 64 + 2 * lane];
            a0 = fma2(W0[m], hv, a0);
            a1 = fma2(W1[m], hv, a1);
            a2 = fma2(W2[m], hv, a2);
            a3 = fma2(W3[m], hv, a3);
        }
        float s0 = lo_f(a0) + hi_f(a0);
        float s1 = lo_f(a1) + hi_f(a1);
        float s2 = lo_f(a2) + hi_f(a2);
        float s3 = lo_f(a3) + hi_f(a3);
#pragma unroll
        for (int off = 16; off; off >>= 1) {
            s0 += __shfl_xor_sync(0xffffffffu, s0, off);
            s1 += __shfl_xor_sync(0xffffffffu, s1, off);
            s2 += __shfl_xor_sync(0xffffffffu, s2, off);
            s3 += __shfl_xor_sync(0xffffffffu, s3, off);
        }

        // lanes 0..3 apply their gate's nonlinearity in parallel
        float sv = (lane == 0) ? s0 : (lane == 1) ? s1 : (lane == 2) ? s2 : s3;
        float g  = (lane == 2) ? ftanh(sv + xv) : fsigmoid(sv + xv);
        float gi = __shfl_sync(0xffffffffu, g, 0);
        float gf = __shfl_sync(0xffffffffu, g, 1);
        float gc = __shfl_sync(0xffffffffu, g, 2);
        float go = __shfl_sync(0xffffffffu, g, 3);

        c = gf * c + gi * gc;               // replicated across lanes (deterministic)
        float h = go * ftanh(c);
        if (lane == 0) sh_out[warp] = h;    // stage this warp's h
        __syncthreads();                    // h staged; also parks warps (protective)
        if (warp == 0 && lane < 8) {
            // one coalesced 64B publish wavefront for the whole CTA
            unsigned long long w =
                ((unsigned long long)(tagbase + (unsigned)t + 1u) << 32) |
                (unsigned long long)__float_as_uint(sh_out[lane]);
            strelax64(g_hpub + (size_t)t * HID + blockIdx.x * 8 + lane, w);
        }
    }
}

// ================= Phase 3: alpha = sigmoid(h @ W_fc^T + b_fc) =================
__global__ void __launch_bounds__(256) alpha_kernel(const float* __restrict__ Wfc,
                                                    const float* __restrict__ bfc)
{
    const int lane = threadIdx.x & 31;
    const int t = blockIdx.x * 8 + (threadIdx.x >> 5);
    const unsigned long long* hp = g_hpub + (size_t)t * HID;
    float acc = 0.0f;
#pragma unroll
    for (int i = 0; i < 32; i++) {
        unsigned long long w = __ldcg(&hp[i * 32 + lane]);
        acc += lo_f(w) * __ldg(&Wfc[i * 32 + lane]);
    }
#pragma unroll
    for (int off = 16; off; off >>= 1)
        acc += __shfl_xor_sync(0xffffffffu, acc, off);
    if (lane == 0)
        g_alpha[t] = fsigmoid(acc + __ldg(bfc));
}

// ================= Phase 4: parallel scans for gated recurrence + loss ===========
// out layout: [0]=loss, [1..N]=y_seq, [1+N..1+2N)=a_seq, [1+2N..1+3N)=u,  N=16383
__global__ void __launch_bounds__(1024) final_kernel(const float* __restrict__ up,
                                                     const float* __restrict__ tl,
                                                     float* __restrict__ out)
{
    const int N = S_LEN - 1;
    __shared__ float sA[1024], sB[1024];
    __shared__ int s_idx;
    const int tid = threadIdx.x;
    const int base = tid * 16;

    if (tid == 0) s_idx = 0x7fffffff;
    __syncthreads();
    {
        int my = 0x7fffffff;
#pragma unroll
        for (int k = 0; k < 16; k++) {
            int i = base + k;
            if (i < N && tl[i] > 0.8f) { my = i; break; }
        }
        if (my != 0x7fffffff) atomicMin(&s_idx, my);
    }

    // ---- local compose of a-recurrence affine maps
    float A = 1.f, B = 0.f;
#pragma unroll
    for (int k = 0; k < 16; k++) {
        int i = base + k;
        float u  = (i < N) ? 1.0f - up[i + 1] : 1.0f;
        float ai = (i < N) ? g_alpha[i + 1]   : 0.0f;
        float Ak = u, Bk = (1.0f - u) * ai;
        B = Ak * B + Bk;
        A = Ak * A;
    }
    sA[tid] = A; sB[tid] = B;
    __syncthreads();
    for (int off = 1; off < 1024; off <<= 1) {
        float aL = 0.f, bL = 0.f;
        if (tid >= off) { aL = sA[tid - off]; bL = sB[tid - off]; }
        float aC = sA[tid], bC = sB[tid];
        __syncthreads();
        if (tid >= off) { sA[tid] = aC * aL; sB[tid] = aC * bL + bC; }
        __syncthreads();
    }
    const float a_prev0 = (tid == 0) ? 0.f : sB[tid - 1];
    __syncthreads();

    // ---- emit a_seq/u, compose y-recurrence maps
    float C = 1.f, D = 0.f;
    {
        float ap = a_prev0;
#pragma unroll
        for (int k = 0; k < 16; k++) {
            int i = base + k;
            float u  = (i < N) ? 1.0f - up[i + 1] : 1.0f;
            float ai = (i < N) ? g_alpha[i + 1]   : 0.0f;
            float ag = u * ap + (1.0f - u) * ai;
            ap = ag;
            if (i < N) {
                out[1 + N + i]     = ag;
                out[1 + 2 * N + i] = u;
                float Ck = 1.0f - ag, Dk = ag * u;
                D = Ck * D + Dk;
                C = Ck * C;
            }
        }
    }
    sA[tid] = C; sB[tid] = D;
    __syncthreads();
    for (int off = 1; off < 1024; off <<= 1) {
        float aL = 0.f, bL = 0.f;
        if (tid >= off) { aL = sA[tid - off]; bL = sB[tid - off]; }
        float aC = sA[tid], bC = sB[tid];
        __syncthreads();
        if (tid >= off) { sA[tid] = aC * aL; sB[tid] = aC * bL + bC; }
        __syncthreads();
    }
    const float y_prev0 = (tid == 0) ? 0.f : sB[tid - 1];

    // ---- emit y_seq
    {
        float ap = a_prev0, yp = y_prev0;
#pragma unroll
        for (int k = 0; k < 16; k++) {
            int i = base + k;
            float u  = (i < N) ? 1.0f - up[i + 1] : 1.0f;
            float ai = (i < N) ? g_alpha[i + 1]   : 0.0f;
            float ag = u * ap + (1.0f - u) * ai;
            ap = ag;
            if (i < N) {
                float y = ag * u + (1.0f - ag) * yp;
                yp = y;
                out[1 + i] = y;
            }
        }
    }
    __syncthreads();

    if (tid == 0) {
        int idx = s_idx;
        bool exists = (idx != 0x7fffffff);
        float loss;
        if (exists) {
            float u_at = 1.0f - up[idx + 1];
            float y_at = out[1 + idx];
            loss = (u_at < 0.5f) ? 0.0f : (y_at - 0.8f) * (y_at - 0.8f);
        } else {
            float yl = out[1 + N - 1];
            loss = (yl >= 0.8f) ? (yl - 0.4f) * (yl - 0.4f) : 0.0f;
        }
        out[0] = loss;
    }
}

// ================= epoch bump (replay-safe monotone tags) =================
__global__ void bump_kernel() { g_epoch = g_epoch + 1u; }

// ================= launch =================
extern "C" void kernel_launch(void* const* d_in, const int* in_sizes, int n_in,
                              void* d_out, int out_size)
{
    const float* inputs    = (const float*)d_in[0];
    const float* uttr_pred = (const float*)d_in[1];
    const float* timing    = (const float*)d_in[2];
    /* d_in[3] uttr_label unused */
    const float* W_ih = (const float*)d_in[4];
    const float* W_hh = (const float*)d_in[5];
    const float* b_ih = (const float*)d_in[6];
    const float* b_hh = (const float*)d_in[7];
    const float* W_fc = (const float*)d_in[8];
    const float* b_fc = (const float*)d_in[9];
    float* out = (float*)d_out;

    fused_kernel<<<NLSTM + NGEMM, 256>>>(inputs, W_ih, b_ih, b_hh, W_hh);
    alpha_kernel<<<S_LEN / 8, 256>>>(W_fc, b_fc);
    final_kernel<<<1, 1024>>>(uttr_pred, timing, out);
    bump_kernel<<<1, 1>>>();
}